// round 4
// baseline (speedup 1.0000x reference)
#include <cuda_runtime.h>

#define DT 0.005f

// ---------------- scratch (no allocation allowed) ----------------
__device__ float    g_partials[4096];
__device__ unsigned g_sem = 0;
__device__ float4   g_coef[8192];   // fallback path only

// fallback float2 swizzle
__device__ __forceinline__ int swz(int t)  { return t ^ ((t >> 4) & 15); }
// float4-pair swizzle: 8-group XOR keeps LDS.128 conflict-free in all phases
__device__ __forceinline__ int swz4(int s) { return s ^ ((s >> 3) & 7); }

__device__ __forceinline__ void cp16(unsigned dst, const void* src) {
    asm volatile("cp.async.cg.shared.global [%0], [%1], 16;\n" :: "r"(dst), "l"(src));
}
__device__ __forceinline__ void cp_commit() { asm volatile("cp.async.commit_group;\n"); }
template <int N>
__device__ __forceinline__ void cp_wait() { asm volatile("cp.async.wait_group %0;\n" :: "n"(N)); }

// ============================================================================
// Fused kernel, T=4096, 256 thr, CHUNK=16 (8 float4 pairs). 1 CTA per row,
// single wave at 4 CTAs/SM.
//  - cp.async stages pred (32KB, swizzled) AND prefetches first half of targ
//    (16KB) so DRAM stays busy through the scan/pass2 compute bubble
//  - gains: steady closed form + 96-step transient table (divide-free Mobius)
//  - 4-component block scan (G,H,Bx,By); steady threads use G=g^16, H=h16
//  - pass2 overwrites pred pairs in smem with windowed pred part P
//  - pass3: first half targ from smem, second half coalesced LDG.128
// ============================================================================
__global__ void __launch_bounds__(256, 4)
kf_fused(const float* __restrict__ pred, const float* __restrict__ targ,
         const float* __restrict__ qv_p, const float* __restrict__ r_p,
         float* __restrict__ out, int B)
{
    constexpr int NT    = 256;
    constexpr int CHUNK = 16;
    constexpr int T     = NT * CHUNK;
    constexpr int NP    = T / 2;        // 2048 float4 pairs
    constexpr int TTR   = 96;           // transient length

    extern __shared__ float4 dyn[];
    float4* sz4 = dyn;                  // [NP]    pred pairs (swizzled), later P
    float4* st4 = dyn + NP;             // [NP/2]  targ pairs, first half (linear)

    __shared__ float4 s_tc[TTR];        // transient (g, kv, u, inv)
    __shared__ float4 s_st;             // (g*, kv*, u*, inv*)
    __shared__ float4 s_st2;            // (g^16, h16, r*u*, -)
    __shared__ float  sWG[8], sWH[8], sWBx[8], sWBy[8];
    __shared__ float  sred[8];
    __shared__ float  sf[256];
    __shared__ int    s_last;

    const int j    = threadIdx.x;
    const int bb   = blockIdx.x;
    const int lane = j & 31;
    const int wrp  = j >> 5;
    const int t0   = j * CHUNK;
    const int p0   = j * (CHUNK / 2);

    const float qv = *qv_p;
    const float r  = *r_p;

    const unsigned sz4a = (unsigned)__cvta_generic_to_shared(sz4);
    const unsigned st4a = (unsigned)__cvta_generic_to_shared(st4);

    // ---- async stage: pred (group 0), then half of targ (group 1) ----
    const float4* gp = (const float4*)(pred + (size_t)bb * T * 2);
    #pragma unroll
    for (int k = 0; k < 8; ++k) {
        int m = j + k * NT;
        cp16(sz4a + 16u * (unsigned)swz4(m), gp + m);
    }
    cp_commit();
    const float4* gt = (const float4*)(targ + (size_t)bb * T * 2);
    #pragma unroll
    for (int k = 0; k < 4; ++k) {
        int m = j + k * NT;
        cp16(st4a + 16u * (unsigned)m, gt + m);
    }
    cp_commit();

    // ---- steady-state gains (thread 0) ----
    if (j == 0) {
        float cstar = 0.5f * (sqrtf(fmaf(qv, qv, 4.f * r * qv)) - qv);
        float cps   = cstar + qv;
        float Ss    = cps + r;
        float invs  = 1.0f / Ss;
        float kvs   = cps * invs;
        float gs    = 1.0f - kvs;
        float us    = DT * cstar * invs;
        s_st = make_float4(gs, kvs, us, invs);
        float g2 = gs * gs, g4 = g2 * g2, g8 = g4 * g4, g16 = g8 * g8;
        float ru = r * us;
        float h16 = ru * (1.f - g16) / kvs;    // ru*(1-g^16)/(1-g), 1-g = kv
        s_st2 = make_float4(g16, h16, ru, 0.f);
    }

    // ---- transient gain table: threads j<6 fill s_tc[16j..16j+15] ----
    if (t0 < TTR) {
        const float r64   = 64.f * r;
        const float rqv64 = 64.f * r * qv;
        const float qvr   = qv + r;
        const float qvr64 = 64.f * qvr;
        float p = 1.f, q = 1.f;                       // c0 = 1
        for (int s = 0; s < t0; ++s) {
            float pn = fmaf(r64, p, rqv64 * q);
            float qn = fmaf(qvr64, q, 64.f * p);
            p = pn; q = qn;
        }
        #pragma unroll
        for (int i = 0; i < CHUNK; ++i) {
            float num  = fmaf(qv,  q, p);
            float den  = fmaf(qvr, q, p);
            float invd = 1.0f / den;
            float kv   = num * invd;
            float inv  = q * invd;
            float u    = DT * p * invd;
            s_tc[t0 + i] = make_float4(1.0f - kv, kv, u, inv);
            float pn = fmaf(r64, p, rqv64 * q);
            float qn = fmaf(qvr64, q, 64.f * p);
            p = pn; q = qn;
        }
    }

    cp_wait<1>();        // pred group landed (targ group may still fly)
    __syncthreads();

    const float4 st  = s_st;
    const float4 st2 = s_st2;

    // ---- pass 1: local affine composition ----
    float G, H, Bx = 0.f, By = 0.f;
    if (t0 < TTR) {
        G = 1.f; H = 0.f;
        #pragma unroll
        for (int i = 0; i < CHUNK / 2; ++i) {
            float4 Z  = sz4[swz4(p0 + i)];
            float4 c0 = s_tc[t0 + 2 * i];
            float4 c1 = s_tc[t0 + 2 * i + 1];
            H  = fmaf(c0.x, H,  r * c0.z);
            Bx = fmaf(c0.x, Bx, c0.y * Z.x);
            By = fmaf(c0.x, By, c0.y * Z.y);
            H  = fmaf(c1.x, H,  r * c1.z);
            Bx = fmaf(c1.x, Bx, c1.y * Z.z);
            By = fmaf(c1.x, By, c1.y * Z.w);
            G *= c0.x * c1.x;
        }
    } else {
        const float g = st.x, kv = st.y;
        G = st2.x; H = st2.y;                  // closed-form g^16, h16
        #pragma unroll
        for (int i = 0; i < CHUNK / 2; ++i) {
            float4 Z = sz4[swz4(p0 + i)];
            Bx = fmaf(g, Bx, kv * Z.x);
            By = fmaf(g, By, kv * Z.y);
            Bx = fmaf(g, Bx, kv * Z.z);
            By = fmaf(g, By, kv * Z.w);
        }
    }

    // ---- combined block scan of (G | H, Bx, By) ----
    #pragma unroll
    for (int off = 1; off < 32; off <<= 1) {
        float pG  = __shfl_up_sync(0xffffffffu, G,  off);
        float pH  = __shfl_up_sync(0xffffffffu, H,  off);
        float pBx = __shfl_up_sync(0xffffffffu, Bx, off);
        float pBy = __shfl_up_sync(0xffffffffu, By, off);
        if (lane >= off) {
            H  = fmaf(G, pH,  H);
            Bx = fmaf(G, pBx, Bx);
            By = fmaf(G, pBy, By);
            G *= pG;
        }
    }
    float eG  = __shfl_up_sync(0xffffffffu, G,  1);
    float eH  = __shfl_up_sync(0xffffffffu, H,  1);
    float eBx = __shfl_up_sync(0xffffffffu, Bx, 1);
    float eBy = __shfl_up_sync(0xffffffffu, By, 1);
    if (lane == 0) { eG = 1.f; eH = 0.f; eBx = 0.f; eBy = 0.f; }
    if (lane == 31) { sWG[wrp] = G; sWH[wrp] = H; sWBx[wrp] = Bx; sWBy[wrp] = By; }
    __syncthreads();
    if (j < 8) {
        float wG = sWG[j], wH = sWH[j], wBx = sWBx[j], wBy = sWBy[j];
        #pragma unroll
        for (int off = 1; off < 8; off <<= 1) {
            float pG  = __shfl_up_sync(0xffu, wG,  off);
            float pH  = __shfl_up_sync(0xffu, wH,  off);
            float pBx = __shfl_up_sync(0xffu, wBx, off);
            float pBy = __shfl_up_sync(0xffu, wBy, off);
            if (j >= off) {
                wH  = fmaf(wG, pH,  wH);
                wBx = fmaf(wG, pBx, wBx);
                wBy = fmaf(wG, pBy, wBy);
                wG *= pG;
            }
        }
        float xG  = __shfl_up_sync(0xffu, wG,  1);
        float xH  = __shfl_up_sync(0xffu, wH,  1);
        float xBx = __shfl_up_sync(0xffu, wBx, 1);
        float xBy = __shfl_up_sync(0xffu, wBy, 1);
        if (j == 0) { xG = 1.f; xH = 0.f; xBx = 0.f; xBy = 0.f; }
        sWG[j] = xG; sWH[j] = xH; sWBx[j] = xBx; sWBy[j] = xBy;
    }
    __syncthreads();
    float b  = fmaf(eG, sWH[wrp],  eH);    // b at chunk entry (b0 = 0)
    float vx = fmaf(eG, sWBx[wrp], eBx);   // v_{t0-1}
    float vy = fmaf(eG, sWBy[wrp], eBy);

    // ---- pass 2: replay, overwrite pred pairs with P pairs ----
    if (t0 < TTR) {
        #pragma unroll
        for (int i = 0; i < CHUNK / 2; ++i) {
            int s = p0 + i;
            float4 Z  = sz4[swz4(s)];
            float4 c0 = s_tc[t0 + 2 * i];
            float4 c1 = s_tc[t0 + 2 * i + 1];
            float kp0 = fmaf(b, c0.w, c0.z);  b = r * kp0;
            float dx0 = Z.x - vx, dy0 = Z.y - vy;
            float Px0 = fmaf(kp0, dx0, DT * vx);
            float Py0 = fmaf(kp0, dy0, DT * vy);
            vx = fmaf(c0.y, dx0, vx); vy = fmaf(c0.y, dy0, vy);
            float kp1 = fmaf(b, c1.w, c1.z);  b = r * kp1;
            float dx1 = Z.z - vx, dy1 = Z.w - vy;
            float Px1 = fmaf(kp1, dx1, DT * vx);
            float Py1 = fmaf(kp1, dy1, DT * vy);
            vx = fmaf(c1.y, dx1, vx); vy = fmaf(c1.y, dy1, vy);
            sz4[swz4(s)] = make_float4(Px0, Py0, Px1, Py1);
        }
    } else {
        const float kv = st.y, u = st.z, inv = st.w;
        #pragma unroll
        for (int i = 0; i < CHUNK / 2; ++i) {
            int s = p0 + i;
            float4 Z = sz4[swz4(s)];
            float kp0 = fmaf(b, inv, u);  b = r * kp0;
            float dx0 = Z.x - vx, dy0 = Z.y - vy;
            float Px0 = fmaf(kp0, dx0, DT * vx);
            float Py0 = fmaf(kp0, dy0, DT * vy);
            vx = fmaf(kv, dx0, vx); vy = fmaf(kv, dy0, vy);
            float kp1 = fmaf(b, inv, u);  b = r * kp1;
            float dx1 = Z.z - vx, dy1 = Z.w - vy;
            float Px1 = fmaf(kp1, dx1, DT * vx);
            float Py1 = fmaf(kp1, dy1, DT * vy);
            vx = fmaf(kv, dx1, vx); vy = fmaf(kv, dy1, vy);
            sz4[swz4(s)] = make_float4(Px0, Py0, Px1, Py1);
        }
    }
    cp_wait<0>();        // targ first half landed long ago
    __syncthreads();

    // ---- pass 3: loss (first half targ from smem, second half gmem) ----
    float acc = 0.f;
    #pragma unroll
    for (int k = 0; k < 8; ++k) {
        int m = j + k * NT;
        float4 w = (k < 4) ? st4[m] : gt[m];
        float4 P = sz4[swz4(m)];
        if (m != 0) {                         // t = 0 has no loss term
            float ex = fmaf(-DT, w.x, P.x);
            float ey = fmaf(-DT, w.y, P.y);
            acc = fmaf(ex, ex, fmaf(ey, ey, acc));
        }
        float ex1 = fmaf(-DT, w.z, P.z);
        float ey1 = fmaf(-DT, w.w, P.w);
        acc = fmaf(ex1, ex1, fmaf(ey1, ey1, acc));
    }

    // ---- block reduce -> partial ----
    #pragma unroll
    for (int o = 16; o; o >>= 1) acc += __shfl_down_sync(0xffffffffu, acc, o);
    if (lane == 0) sred[wrp] = acc;
    __syncthreads();
    if (j == 0) {
        float v = 0.f;
        #pragma unroll
        for (int wv = 0; wv < 8; ++wv) v += sred[wv];
        g_partials[bb] = v;
        __threadfence();
        unsigned done = atomicAdd(&g_sem, 1u);
        s_last = (done == (unsigned)gridDim.x - 1u);
    }
    __syncthreads();

    // ---- last CTA: deterministic final reduction + semaphore reset ----
    if (s_last) {
        __threadfence();
        float v = 0.f;
        for (int i = j; i < B; i += NT) v += g_partials[i];
        sf[j] = v;
        __syncthreads();
        for (int o = 128; o; o >>= 1) {
            if (j < o) sf[j] += sf[j + o];
            __syncthreads();
        }
        if (j == 0) {
            out[0] = sf[0] / ((float)B * (float)(T - 1) * 2.f);
            atomicExch(&g_sem, 0u);
        }
    }
}

// ============================================================================
// Fallback path (any T) — proven Round-1 kernels
// ============================================================================
__global__ void kf_setup(const float* __restrict__ q_vel_p,
                         const float* __restrict__ r_vel_p, int T) {
    __shared__ float skp[4096];
    __shared__ float skv[4096];
    __shared__ int   s_conv;
    __shared__ float s_kp_last, s_kv_last;

    int Tser = T < 4096 ? T : 4096;
    if (threadIdx.x == 0) {
        float qvv = *q_vel_p;
        float rr  = *r_vel_p;
        float bb = 0.f, cc = 1.f;
        float kp = 0.f, kv = 0.f;
        int tconv = Tser;
        for (int t = 0; t < Tser; ++t) {
            float cp  = cc + qvv;
            float bp  = fmaf(DT, cc, bb);
            float S   = cp + rr;
            float inv = __fdividef(1.f, S);
            kv = cp * inv;
            kp = bp * inv;
            skp[t] = kp; skv[t] = kv;
            float rs = rr * inv;
            float nc = cp * rs;
            float nb = bp * rs;
            if (nc == cc && nb == bb) { tconv = t + 1; break; }
            cc = nc; bb = nb;
        }
        s_conv = tconv; s_kp_last = kp; s_kv_last = kv;
    }
    __syncthreads();
    int   tconv = s_conv;
    float kpl = s_kp_last, kvl = s_kv_last;
    for (int t = threadIdx.x; t < T; t += blockDim.x) {
        float kp = (t < tconv) ? skp[t] : kpl;
        float kv = (t < tconv) ? skv[t] : kvl;
        g_coef[t] = make_float4(1.f - kv, kv, DT - kp, kp);
    }
}

__global__ void __launch_bounds__(256)
kf_main(const float* __restrict__ pred, const float* __restrict__ targ, int T) {
    extern __shared__ float2 sp2[];
    const int NT = 256;
    int j = threadIdx.x, bb = blockIdx.x;

    const float4* gp = (const float4*)(pred + (size_t)bb * T * 2);
    int n4 = (T * 2) / 4;
    for (int m = j; m < n4; m += NT) {
        float4 v = gp[m];
        sp2[swz(2 * m)]     = make_float2(v.x, v.y);
        sp2[swz(2 * m + 1)] = make_float2(v.z, v.w);
    }
    __syncthreads();

    int chunk = (T + NT - 1) / NT;
    int t0 = j * chunk;

    float A = 1.f, Bx = 0.f, By = 0.f;
    for (int i = 0; i < chunk; ++i) {
        int t = t0 + i;
        if (t >= T) break;
        float4 cf = g_coef[t];
        float2 z  = sp2[swz(t)];
        A  = A * cf.x;
        Bx = fmaf(cf.x, Bx, cf.y * z.x);
        By = fmaf(cf.x, By, cf.y * z.y);
    }

    __shared__ float sA[256], sBx[256], sBy[256];
    sA[j] = A; sBx[j] = Bx; sBy[j] = By;
    __syncthreads();
    for (int off = 1; off < NT; off <<= 1) {
        float a2 = 0.f, bx2 = 0.f, by2 = 0.f;
        bool act = (j >= off);
        if (act) {
            float ap = sA[j - off], bxp = sBx[j - off], byp = sBy[j - off];
            a2  = A * ap;
            bx2 = fmaf(A, bxp, Bx);
            by2 = fmaf(A, byp, By);
        }
        __syncthreads();
        if (act) { A = a2; Bx = bx2; By = by2; sA[j] = A; sBx[j] = Bx; sBy[j] = By; }
        __syncthreads();
    }
    float vx = (j == 0) ? 0.f : sBx[j - 1];
    float vy = (j == 0) ? 0.f : sBy[j - 1];

    const float2* gt2 = (const float2*)(targ + (size_t)bb * T * 2);
    float acc = 0.f;
    for (int i = 0; i < chunk; ++i) {
        int t = t0 + i;
        if (t >= T) break;
        float4 cf = g_coef[t];
        float2 z  = sp2[swz(t)];
        if (t > 0) {
            float2 w = gt2[t];
            float ex = fmaf(cf.z, vx, fmaf(cf.w, z.x, -DT * w.x));
            float ey = fmaf(cf.z, vy, fmaf(cf.w, z.y, -DT * w.y));
            acc = fmaf(ex, ex, fmaf(ey, ey, acc));
        }
        vx = fmaf(cf.x, vx, cf.y * z.x);
        vy = fmaf(cf.x, vy, cf.y * z.y);
    }

    for (int o = 16; o; o >>= 1) acc += __shfl_down_sync(0xffffffffu, acc, o);
    __shared__ float swsum[8];
    if ((j & 31) == 0) swsum[j >> 5] = acc;
    __syncthreads();
    if (j < 8) {
        float v = swsum[j];
        v += __shfl_down_sync(0xffu, v, 4);
        v += __shfl_down_sync(0xffu, v, 2);
        v += __shfl_down_sync(0xffu, v, 1);
        if (j == 0) g_partials[bb] = v;
    }
}

__global__ void kf_reduce(float* __restrict__ out, int B, int T) {
    __shared__ float s[256];
    float v = 0.f;
    for (int i = threadIdx.x; i < B; i += blockDim.x) v += g_partials[i];
    s[threadIdx.x] = v;
    __syncthreads();
    for (int o = 128; o; o >>= 1) {
        if (threadIdx.x < o) s[threadIdx.x] += s[threadIdx.x + o];
        __syncthreads();
    }
    if (threadIdx.x == 0)
        out[0] = s[0] / ((float)B * (float)(T - 1) * 2.f);
}

extern "C" void kernel_launch(void* const* d_in, const int* in_sizes, int n_in,
                              void* d_out, int out_size) {
    // metadata order: pred_vel, targ_vel, q_pos, q_vel, r_vel, p0
    const float* pred  = (const float*)d_in[0];
    const float* targ  = (const float*)d_in[1];
    const float* q_vel = (const float*)d_in[3];
    const float* r_vel = (const float*)d_in[4];
    int B = in_sizes[5] / 2;          // p0 is (B, 2)
    int T = in_sizes[0] / (B * 2);    // pred_vel is (B, T, 2)

    if (T == 4096 && B <= 4096) {
        const int dynsmem = (2048 + 1024) * (int)sizeof(float4);   // 48 KB
        cudaFuncSetAttribute(kf_fused, cudaFuncAttributeMaxDynamicSharedMemorySize, dynsmem);
        kf_fused<<<B, 256, dynsmem>>>(pred, targ, q_vel, r_vel, (float*)d_out, B);
    } else {
        kf_setup<<<1, 256>>>(q_vel, r_vel, T);
        size_t sh = (size_t)T * sizeof(float2);
        kf_main<<<B, 256, sh>>>(pred, targ, T);
        kf_reduce<<<1, 256>>>((float*)d_out, B, T);
    }
}